// round 15
// baseline (speedup 1.0000x reference)
#include <cuda_runtime.h>
#include <cuda_bf16.h>

// Output: [Cm1, 1, R, 85] fp32 flat (NC = 81). One-pass specialized kernel.
// R14 structure (proven 170.7us) + CGRP=2: each thread loads its cls float4
// once and streams it to TWO adjacent class planes, halving cls L2 read
// traffic while preserving the per-block contiguous store topology.
//
// Group structure: 4 rows = 340 elements = exactly 85 float4s.
// Boundary float4 positions (touch box slots): {20,21,41,42,62,63,84}.
// Fast remap: w in [0,78) -> p = w + 2*cnt, cnt=(w>=20)+(w>=39)+(w>=58);
//             cls float4 idx = 81g + w + cnt.

__global__ void __launch_bounds__(256)
bb_pair_kernel(const float* __restrict__ cls,     // [R, 81]
               const float4* __restrict__ cls4,
               const float4* __restrict__ regr4,  // [R, Cm1] of float4
               const float4* __restrict__ rois,   // [R] of float4
               float4* __restrict__ out4,
               int perC4,        // 85*R/4
               int R, int Cm1,
               int fastBlocks,   // ceil(fastCount/512)
               int fastCount,    // 78*(R/4)
               int slowCount,    // 7*(R/4)
               float invW, float invH)
{
    const int c0 = blockIdx.y * 2;
    const int c1 = c0 + 1;
    const bool c1ok = (c1 < Cm1);
    float4* plane0 = out4 + (size_t)c0 * (size_t)perC4;
    float4* plane1 = plane0 + perC4;

    if (blockIdx.x < (unsigned)fastBlocks) {
        // ---------- FAST: 2 positions/thread, each stored to 2 planes ----------
        int base = blockIdx.x * 512 + threadIdx.x;
#pragma unroll
        for (int s = 0; s < 2; ++s) {
            int tf = base + s * 256;
            if (tf < fastCount) {
                unsigned w = (unsigned)tf % 78u;          // const-div
                unsigned g = (unsigned)tf / 78u;
                unsigned cnt = (w >= 20u) + (w >= 39u) + (w >= 58u);
                int t   = (int)(85u * g + w + 2u * cnt);  // plane float4 index
                int idx = (int)(81u * g + w + cnt);       // cls float4 index
                float4 v = __ldg(&cls4[idx]);
                __stcs(&plane0[t], v);
                if (c1ok) __stcs(&plane1[t], v);
            }
        }
        return;
    }

    // ---------- SLOW: boundary float4s (contain box elements) ----------
    int u = (blockIdx.x - fastBlocks) * 256 + threadIdx.x;
    if (u >= slowCount) return;
    unsigned q = (unsigned)u % 7u;
    unsigned g = (unsigned)u / 7u;
    unsigned p = (q == 6u) ? 84u : (20u + 21u * (q >> 1) + (q & 1u));
    int t = (int)(85u * g + p);

    unsigned rem0 = (unsigned)t << 2;
    unsigned r  = rem0 / 85u;
    unsigned k0 = rem0 - r * 85u;

    float4 roi = __ldg(&rois[r]);                     // x, y, w, h (c-invariant)

    // Class-invariant blend setup: cls scalar or box component id per lane elem.
    float clsv[4];
    int   comp[4];                                    // -1 => cls, else 0..3
#pragma unroll
    for (int i = 0; i < 4; ++i) {
        int k = (int)k0 + i;
        int rr = (int)r;
        if (k >= 85) { k -= 85; ++rr; }               // wrap to next row's cls
        if (k < 81) { comp[i] = -1; clsv[i] = __ldg(&cls[(size_t)rr * 81 + k]); }
        else        { comp[i] = k - 81; clsv[i] = 0.0f; }
    }

#pragma unroll
    for (int cc = 0; cc < 2; ++cc) {
        int c = c0 + cc;
        if (cc == 1 && !c1ok) break;
        float4 tg = __ldg(&regr4[(size_t)r * Cm1 + c]);   // tx, ty, tw, th
        float gx = rintf(fmaf(roi.z, tg.x, roi.x));
        float gy = rintf(fmaf(roi.w, tg.y, roi.y));
        float gw = rintf(roi.z * expf(tg.z));
        float gh = rintf(roi.w * expf(tg.w));
        float b0 = gx * invW;
        float b1 = gy * invH;
        float b2 = (gx + gw) * invW;
        float b3 = (gy + gh) * invH;

        float v[4];
#pragma unroll
        for (int i = 0; i < 4; ++i) {
            float bv = (comp[i] == 0) ? b0 :
                       (comp[i] == 1) ? b1 :
                       (comp[i] == 2) ? b2 : b3;
            v[i] = (comp[i] < 0) ? clsv[i] : bv;
        }
        float4 o; o.x = v[0]; o.y = v[1]; o.z = v[2]; o.w = v[3];
        __stcs((cc == 0) ? &plane0[t] : &plane1[t], o);
    }
}

// ---------------- Generic scalar fallback ----------------
__global__ void __launch_bounds__(256)
bb_generic_kernel(const float* __restrict__ regr, const float* __restrict__ cls,
                  const float4* __restrict__ rois, float* __restrict__ out,
                  int R, int Cm1, int NC, float invW, float invH, long long total)
{
    long long idx = (long long)blockIdx.x * blockDim.x + threadIdx.x;
    long long stride = (long long)gridDim.x * blockDim.x;
    const int rowlen = NC + 4;
    const long long perC = (long long)R * rowlen;
    for (; idx < total; idx += stride) {
        int c   = (int)(idx / perC);
        int rem = (int)(idx - (long long)c * perC);
        int r   = rem / rowlen;
        int k   = rem - r * rowlen;
        float val;
        if (k < NC) {
            val = cls[(long long)r * NC + k];
        } else {
            float4 roi = __ldg(&rois[r]);
            const float* rg = regr + ((long long)r * Cm1 + c) * 4;
            int comp = k - NC;
            if (comp == 0)      val = rintf(fmaf(roi.z, rg[0], roi.x)) * invW;
            else if (comp == 1) val = rintf(fmaf(roi.w, rg[1], roi.y)) * invH;
            else if (comp == 2) val = (rintf(fmaf(roi.z, rg[0], roi.x)) +
                                       rintf(roi.z * expf(rg[2]))) * invW;
            else                val = (rintf(fmaf(roi.w, rg[1], roi.y)) +
                                       rintf(roi.w * expf(rg[3]))) * invH;
        }
        out[idx] = val;
    }
}

extern "C" void kernel_launch(void* const* d_in, const int* in_sizes, int n_in,
                              void* d_out, int out_size)
{
    const float*  regr = (const float*)d_in[0];   // [1, R, 4*Cm1]
    const float*  cls  = (const float*)d_in[1];   // [1, R, NC]
    const float4* rois = (const float4*)d_in[2];  // [1, R, 4]

    const int R   = in_sizes[2] / 4;
    const int Cm1 = in_sizes[0] / (R * 4);
    const int NC  = in_sizes[1] / R;
    const int rowlen = NC + 4;

    long long hw = (long long)in_sizes[3] / 3;    // H = W = isqrt(b_elems/3)
    int side = 1;
    while ((long long)(side + 1) * (side + 1) <= hw) ++side;
    const float invW = 1.0f / (float)side;
    const float invH = 1.0f / (float)side;

    float* out = (float*)d_out;
    const long long perC  = (long long)R * rowlen;
    const long long total = (long long)out_size;

    if (rowlen == 85 && (R % 4) == 0 &&
        total == (long long)Cm1 * perC && (perC % 4) == 0) {
        const int perC4     = (int)(perC >> 2);
        const int groups    = R / 4;
        const int fastCount = 78 * groups;
        const int slowCount = 7 * groups;
        const int fastBlocks = (fastCount + 511) / 512;
        const int slowBlocks = (slowCount + 255) / 256;
        dim3 grid(fastBlocks + slowBlocks, (Cm1 + 1) / 2);
        bb_pair_kernel<<<grid, 256>>>(
            cls, (const float4*)cls, (const float4*)regr, rois,
            (float4*)out, perC4, R, Cm1,
            fastBlocks, fastCount, slowCount, invW, invH);
    } else {
        long long blocks = (total + 255) / 256;
        if (blocks > 262144) blocks = 262144;
        bb_generic_kernel<<<(unsigned)blocks, 256>>>(
            regr, cls, rois, out, R, Cm1, NC, invW, invH, total);
    }
}

// round 16
// speedup vs baseline: 1.2020x; 1.2020x over previous
#include <cuda_runtime.h>
#include <cuda_bf16.h>

// Output: [Cm1, 1, R, 85] fp32 flat (NC = 81).
//
// Dense one-pass kernel. Group = 4 rows = 340 elems = 85 float4s.
// Boundary float4 positions in a group (touch box slots): {20,21,41,42,62,63,84}.
// Each block owns 8 groups = 680 contiguous float4s (= 85 aligned 128B sectors)
// of one class plane and writes ALL of them exactly once:
//   tasks 0..623  : fast cls copies (remap w -> p skips boundary positions)
//   tasks 624..679: boundary float4s (box math + cls blend)
// 256 threads x 3 tasks (stride 256). Tasks #1,#2 are always fast; only task #3
// mixes fast/boundary, so expf divergence is confined to a few warps' last step.

__global__ void __launch_bounds__(256)
bb_dense_kernel(const float* __restrict__ cls,     // [R, 81]
                const float4* __restrict__ cls4,
                const float4* __restrict__ regr4,  // [R, Cm1] of float4
                const float4* __restrict__ rois,   // [R] of float4
                float4* __restrict__ out4,
                int perC4,        // 85*R/4
                int R, int Cm1,
                float invW, float invH)
{
    const int c = blockIdx.y;
    float4* plane = out4 + (size_t)c * (size_t)perC4;
    const int gbase  = blockIdx.x * 8;       // first group of this block
    const int tbase  = blockIdx.x * 680;     // first plane float4 of this block

#pragma unroll
    for (int s = 0; s < 3; ++s) {
        int v = threadIdx.x + s * 256;       // task id in [0, 680)
        if (v >= 680) break;

        if (v < 624) {
            // ---------- FAST: pure cls copy ----------
            unsigned w  = (unsigned)v % 78u;         // const-div
            unsigned gg = (unsigned)v / 78u;         // group in block, 0..7
            unsigned cnt = (w >= 20u) + (w >= 39u) + (w >= 58u);
            int loc = (int)(85u * gg + w + 2u * cnt);            // pos in block
            int idx = (int)(81u * (unsigned)(gbase + (int)gg) + w + cnt);
            float4 val = __ldg(&cls4[idx]);
            __stcs(&plane[tbase + loc], val);
        } else {
            // ---------- BOUNDARY: box math + cls blend ----------
            unsigned ub = (unsigned)(v - 624);       // 0..55
            unsigned q  = ub % 7u;
            unsigned gg = ub / 7u;
            unsigned p  = (q == 6u) ? 84u : (20u + 21u * (q >> 1) + (q & 1u));
            int t = tbase + (int)(85u * gg + p);

            unsigned rem0 = (unsigned)t << 2;
            unsigned r  = rem0 / 85u;
            unsigned k0 = rem0 - r * 85u;

            float4 roi = __ldg(&rois[r]);                      // x, y, w, h
            float4 tg  = __ldg(&regr4[(size_t)r * Cm1 + c]);   // tx, ty, tw, th

            float gx = rintf(fmaf(roi.z, tg.x, roi.x));
            float gy = rintf(fmaf(roi.w, tg.y, roi.y));
            float gw = rintf(roi.z * expf(tg.z));
            float gh = rintf(roi.w * expf(tg.w));

            float b[4];
            b[0] = gx * invW;
            b[1] = gy * invH;
            b[2] = (gx + gw) * invW;
            b[3] = (gy + gh) * invH;

            float vv[4];
#pragma unroll
            for (int i = 0; i < 4; ++i) {
                int k = (int)k0 + i;
                int rr = (int)r;
                if (k >= 85) { k -= 85; ++rr; }   // wrap to next row's cls
                vv[i] = (k < 81) ? __ldg(&cls[(size_t)rr * 81 + k]) : b[k - 81];
            }
            float4 o; o.x = vv[0]; o.y = vv[1]; o.z = vv[2]; o.w = vv[3];
            __stcs(&plane[t], o);
        }
    }
}

// ---------------- Generic scalar fallback ----------------
__global__ void __launch_bounds__(256)
bb_generic_kernel(const float* __restrict__ regr, const float* __restrict__ cls,
                  const float4* __restrict__ rois, float* __restrict__ out,
                  int R, int Cm1, int NC, float invW, float invH, long long total)
{
    long long idx = (long long)blockIdx.x * blockDim.x + threadIdx.x;
    long long stride = (long long)gridDim.x * blockDim.x;
    const int rowlen = NC + 4;
    const long long perC = (long long)R * rowlen;
    for (; idx < total; idx += stride) {
        int c   = (int)(idx / perC);
        int rem = (int)(idx - (long long)c * perC);
        int r   = rem / rowlen;
        int k   = rem - r * rowlen;
        float val;
        if (k < NC) {
            val = cls[(long long)r * NC + k];
        } else {
            float4 roi = __ldg(&rois[r]);
            const float* rg = regr + ((long long)r * Cm1 + c) * 4;
            int comp = k - NC;
            if (comp == 0)      val = rintf(fmaf(roi.z, rg[0], roi.x)) * invW;
            else if (comp == 1) val = rintf(fmaf(roi.w, rg[1], roi.y)) * invH;
            else if (comp == 2) val = (rintf(fmaf(roi.z, rg[0], roi.x)) +
                                       rintf(roi.z * expf(rg[2]))) * invW;
            else                val = (rintf(fmaf(roi.w, rg[1], roi.y)) +
                                       rintf(roi.w * expf(rg[3]))) * invH;
        }
        out[idx] = val;
    }
}

extern "C" void kernel_launch(void* const* d_in, const int* in_sizes, int n_in,
                              void* d_out, int out_size)
{
    const float*  regr = (const float*)d_in[0];   // [1, R, 4*Cm1]
    const float*  cls  = (const float*)d_in[1];   // [1, R, NC]
    const float4* rois = (const float4*)d_in[2];  // [1, R, 4]

    const int R   = in_sizes[2] / 4;
    const int Cm1 = in_sizes[0] / (R * 4);
    const int NC  = in_sizes[1] / R;
    const int rowlen = NC + 4;

    long long hw = (long long)in_sizes[3] / 3;    // H = W = isqrt(b_elems/3)
    int side = 1;
    while ((long long)(side + 1) * (side + 1) <= hw) ++side;
    const float invW = 1.0f / (float)side;
    const float invH = 1.0f / (float)side;

    float* out = (float*)d_out;
    const long long perC  = (long long)R * rowlen;
    const long long total = (long long)out_size;

    if (rowlen == 85 && (R % 32) == 0 &&
        total == (long long)Cm1 * perC && (perC % 4) == 0) {
        // Dense one-pass: 8 groups (= 32 rows = 680 float4s) per block.
        const int perC4  = (int)(perC >> 2);
        const int blocksX = R / 32;               // groups/8
        dim3 grid(blocksX, Cm1);
        bb_dense_kernel<<<grid, 256>>>(
            cls, (const float4*)cls, (const float4*)regr, rois,
            (float4*)out, perC4, R, Cm1, invW, invH);
    } else {
        long long blocks = (total + 255) / 256;
        if (blocks > 262144) blocks = 262144;
        bb_generic_kernel<<<(unsigned)blocks, 256>>>(
            regr, cls, rois, out, R, Cm1, NC, invW, invH, total);
    }
}